// round 4
// baseline (speedup 1.0000x reference)
#include <cuda_runtime.h>
#include <cuda_bf16.h>
#include <float.h>

// Problem constants
#define BB 8
#define CC 64
#define NN 4096
#define KK 20
#define OO 64
#define BNK 655360.0f   // B*N*K

// ---------------- static scratch (device globals; no allocation) ----------------
__device__ float g_d2[(size_t)BB * NN * NN];          // 512 MB distance matrix
__device__ float g_z[(size_t)BB * NN * OO];           // W2 . x_m
__device__ float g_u[(size_t)BB * NN * OO];           // (W1-W2) . x_n + b
__device__ float g_ymax[(size_t)BB * NN * OO];        // u + max_k z
__device__ float g_sq[BB * NN];                       // |x_n|^2
__device__ int   g_idx[BB * NN * KK];                 // knn indices (within batch)
__device__ float g_sum[OO];
__device__ float g_sumsq[OO];
__device__ float g_scale[OO];
__device__ float g_shift[OO];

// ---------------- K_zero: reset accumulators (graph replays!) ----------------
__global__ void k_zero() {
    int t = threadIdx.x;
    if (t < OO) { g_sum[t] = 0.f; g_sumsq[t] = 0.f; }
}

// ---------------- K_prep: sq, z, u ----------------
// grid = B*N/32 = 1024 blocks, 256 threads
__global__ __launch_bounds__(256) void k_prep(const float* __restrict__ x,
                                              const float* __restrict__ W,
                                              const float* __restrict__ bias) {
    __shared__ float xs[32][65];    // [n_local][c]
    __shared__ float W2s[64][65];   // [o][c]
    __shared__ float Wds[64][65];   // [o][c]  (W1-W2)

    int blk = blockIdx.x;
    int b   = blk >> 7;             // 128 tiles of 32 per batch
    int n0  = (blk & 127) * 32;
    int tid = threadIdx.x;

    for (int i = tid; i < 64 * 64; i += 256) {
        int o = i >> 6, c = i & 63;
        float w1 = W[o * 128 + c];
        float w2 = W[o * 128 + 64 + c];
        W2s[o][c] = w2;
        Wds[o][c] = w1 - w2;
    }
    const float* xb = x + (size_t)b * CC * NN;
    for (int i = tid; i < 64 * 32; i += 256) {
        int c = i >> 5, j = i & 31;
        xs[j][c] = xb[c * NN + n0 + j];
    }
    __syncthreads();

    if (tid < 32) {
        float s = 0.f;
        #pragma unroll 16
        for (int c = 0; c < 64; c++) { float v = xs[tid][c]; s += v * v; }
        g_sq[b * NN + n0 + tid] = s;
    }

    for (int i = tid; i < 32 * 64; i += 256) {
        int j = i >> 6, o = i & 63;
        float za = 0.f, ua = bias[o];
        #pragma unroll 16
        for (int c = 0; c < 64; c++) {
            float xv = xs[j][c];
            za = fmaf(W2s[o][c], xv, za);
            ua = fmaf(Wds[o][c], xv, ua);
        }
        size_t pt = (size_t)(b * NN + n0 + j) * OO + o;
        g_z[pt] = za;
        g_u[pt] = ua;
    }
}

// ---------------- K_dist: pairwise d2 GEMM ----------------
// tile 64q x 128m, K=64 fully resident; block 256 threads (16x16), thread tile 4x8.
// grid = (32, 64, 8)
__global__ __launch_bounds__(256) void k_dist(const float* __restrict__ x) {
    __shared__ float sQ[64 * 64];    // [c][q_local]
    __shared__ float sC[64 * 128];   // [c][m_local]

    int b  = blockIdx.z;
    int q0 = blockIdx.y * 64;
    int m0 = blockIdx.x * 128;
    const float* xb = x + (size_t)b * CC * NN;
    int tid = threadIdx.x;

    for (int i = tid; i < 64 * 64; i += 256) {
        int c = i >> 6, j = i & 63;
        sQ[c * 64 + j] = xb[c * NN + q0 + j];
    }
    for (int i = tid; i < 64 * 128; i += 256) {
        int c = i >> 7, j = i & 127;
        sC[c * 128 + j] = xb[c * NN + m0 + j];
    }
    __syncthreads();

    int tx = tid & 15, ty = tid >> 4;   // tx -> m (8 cols), ty -> q (4 rows)
    float acc[4][8];
    #pragma unroll
    for (int i = 0; i < 4; i++)
        #pragma unroll
        for (int j = 0; j < 8; j++) acc[i][j] = 0.f;

    #pragma unroll 8
    for (int c = 0; c < 64; c++) {
        float4 a  = *(const float4*)(sQ + c * 64 + ty * 4);
        float4 b0 = *(const float4*)(sC + c * 128 + tx * 8);
        float4 b1 = *(const float4*)(sC + c * 128 + tx * 8 + 4);
        float av[4] = {a.x, a.y, a.z, a.w};
        float bv[8] = {b0.x, b0.y, b0.z, b0.w, b1.x, b1.y, b1.z, b1.w};
        #pragma unroll
        for (int i = 0; i < 4; i++)
            #pragma unroll
            for (int j = 0; j < 8; j++)
                acc[i][j] = fmaf(av[i], bv[j], acc[i][j]);
    }

    int mg = m0 + tx * 8;
    float sqm[8];
    #pragma unroll
    for (int j = 0; j < 8; j++) sqm[j] = g_sq[b * NN + mg + j];

    #pragma unroll
    for (int i = 0; i < 4; i++) {
        int q = q0 + ty * 4 + i;
        float sqn = g_sq[b * NN + q];
        float o[8];
        #pragma unroll
        for (int j = 0; j < 8; j++) {
            float d = (sqn + sqm[j]) - 2.0f * acc[i][j];
            o[j] = (q == mg + j) ? FLT_MAX : d;   // exclude self
        }
        float* dst = g_d2 + ((size_t)b << 24) + (size_t)q * NN + mg;
        *(float4*)(dst)     = make_float4(o[0], o[1], o[2], o[3]);
        *(float4*)(dst + 4) = make_float4(o[4], o[5], o[6], o[7]);
    }
}

// ---------------- K_select: per row, 20 smallest (tie -> lowest index) ----------------
// one block (128 threads) per row; cached per-thread local argmin + 20 extraction rounds
__global__ __launch_bounds__(128) void k_select() {
    __shared__ float sd[NN];
    __shared__ unsigned long long red[4];

    int row = blockIdx.x;                       // b*N + n
    int tid = threadIdx.x;
    const float* drow = g_d2 + (size_t)row * NN;

    for (int i = tid; i < NN; i += 128) sd[i] = drow[i];
    __syncthreads();

    // thread owns elements {tid, tid+128, ...} -> conflict-free strided scan
    unsigned long long lmin = 0xFFFFFFFFFFFFFFFFull;
    #pragma unroll 8
    for (int e = 0; e < 32; e++) {
        int ix = tid + e * 128;
        unsigned long long key =
            ((unsigned long long)__float_as_uint(sd[ix]) << 32) | (unsigned)ix;
        if (key < lmin) lmin = key;
    }

    for (int r = 0; r < KK; r++) {
        unsigned long long v = lmin;
        #pragma unroll
        for (int s = 16; s; s >>= 1) {
            unsigned long long o = __shfl_down_sync(0xFFFFFFFFu, v, s);
            if (o < v) v = o;
        }
        if ((tid & 31) == 0) red[tid >> 5] = v;
        __syncthreads();
        unsigned long long w = red[0];
        if (red[1] < w) w = red[1];
        if (red[2] < w) w = red[2];
        if (red[3] < w) w = red[3];
        int widx = (int)(w & 0xFFFFFFFFu);
        if (tid == 0) g_idx[row * KK + r] = widx;
        if ((widx & 127) == tid) {
            sd[widx] = FLT_MAX;
            unsigned long long nm = 0xFFFFFFFFFFFFFFFFull;
            #pragma unroll 8
            for (int e = 0; e < 32; e++) {
                int ix = tid + e * 128;
                unsigned long long key =
                    ((unsigned long long)__float_as_uint(sd[ix]) << 32) | (unsigned)ix;
                if (key < nm) nm = key;
            }
            lmin = nm;
        }
        __syncthreads();  // protect red[] before next round's writes
    }
}

// ---------------- K_gather: ymax + BN stats ----------------
// block 256 threads = 4 point-lanes x 64 channels; 16 points/block; grid 2048
__global__ __launch_bounds__(256) void k_gather() {
    __shared__ float s[256];
    int tid = threadIdx.x;
    int pl = tid >> 6, o = tid & 63;
    float rs1 = 0.f, rs2 = 0.f;

    #pragma unroll
    for (int it = 0; it < 4; it++) {
        int pt = blockIdx.x * 16 + it * 4 + pl;     // 0..32767
        int zbase = pt & ~(NN - 1);                 // b*N
        float u = g_u[(size_t)pt * OO + o];
        float m = -FLT_MAX, s1 = 0.f, s2 = 0.f;
        #pragma unroll
        for (int k = 0; k < KK; k++) {
            int nbr = __ldg(&g_idx[pt * KK + k]);
            float z = g_z[(size_t)(zbase + nbr) * OO + o];
            m = fmaxf(m, z);
            s1 += z;
            s2 = fmaf(z, z, s2);
        }
        g_ymax[(size_t)pt * OO + o] = u + m;
        rs1 += 20.f * u + s1;
        rs2 += fmaf(20.f * u, u, fmaf(2.f * u, s1, s2));
    }
    s[tid] = rs1; __syncthreads();
    if (pl == 0) atomicAdd(&g_sum[o], s[o] + s[o + 64] + s[o + 128] + s[o + 192]);
    __syncthreads();
    s[tid] = rs2; __syncthreads();
    if (pl == 0) atomicAdd(&g_sumsq[o], s[o] + s[o + 64] + s[o + 128] + s[o + 192]);
}

// ---------------- K_stats: mean/var -> scale/shift ----------------
__global__ void k_stats(const float* __restrict__ gamma, const float* __restrict__ beta) {
    int o = threadIdx.x;
    if (o < OO) {
        float mean = g_sum[o] / BNK;
        float var  = g_sumsq[o] / BNK - mean * mean;
        float sc   = gamma[o] * rsqrtf(var + 1e-5f);
        g_scale[o] = sc;
        g_shift[o] = beta[o] - mean * sc;
    }
}

// ---------------- K_final: normalize + relu + transpose to (B,O,N) ----------------
// grid = 8 * 128 blocks, 256 threads; tile 32n x 64o via smem transpose
__global__ __launch_bounds__(256) void k_final(float* __restrict__ out) {
    __shared__ float t[64][33];
    int b  = blockIdx.x >> 7;
    int n0 = (blockIdx.x & 127) << 5;
    int tid = threadIdx.x;

    for (int i = tid; i < 2048; i += 256) {
        int r = i >> 6, c = i & 63;
        t[c][r] = g_ymax[(size_t)((b << 12) + n0 + r) * OO + c];
    }
    __syncthreads();
    for (int i = tid; i < 2048; i += 256) {
        int o = i >> 5, nl = i & 31;
        float v = fmaf(t[o][nl], g_scale[o], g_shift[o]);
        out[(size_t)b * OO * NN + (size_t)o * NN + n0 + nl] = fmaxf(v, 0.f);
    }
}

// ---------------- launch ----------------
extern "C" void kernel_launch(void* const* d_in, const int* in_sizes, int n_in,
                              void* d_out, int out_size) {
    const float* x     = (const float*)d_in[0];
    const float* W     = (const float*)d_in[1];
    const float* bias  = (const float*)d_in[2];
    const float* gamma = (const float*)d_in[3];
    const float* beta  = (const float*)d_in[4];
    float* out = (float*)d_out;

    k_zero<<<1, 128>>>();
    k_prep<<<1024, 256>>>(x, W, bias);
    dim3 gd(NN / 128, NN / 64, BB);
    k_dist<<<gd, 256>>>(x);
    k_select<<<BB * NN, 128>>>();
    k_gather<<<2048, 256>>>();
    k_stats<<<1, 64>>>(gamma, beta);
    k_final<<<1024, 256>>>(out);
}

// round 7
// speedup vs baseline: 1.9707x; 1.9707x over previous
#include <cuda_runtime.h>
#include <cuda_bf16.h>
#include <float.h>

// Problem constants
#define BB 8
#define CC 64
#define NN 4096
#define KK 20
#define OO 64
#define BNK 655360.0f   // B*N*K

// ---------------- static scratch ----------------
__device__ float g_d2[(size_t)BB * NN * NN];          // 512 MB distance matrix
__device__ float g_z[(size_t)BB * NN * OO];           // W2 . x_m
__device__ float g_u[(size_t)BB * NN * OO];           // (W1-W2) . x_n + b
__device__ float g_ymax[(size_t)BB * NN * OO];        // u + max_k z
__device__ float g_sq[BB * NN];                       // |x_n|^2
__device__ int   g_idx[BB * NN * KK];                 // knn indices (within batch)
__device__ float g_sum[OO];
__device__ float g_sumsq[OO];
__device__ float g_scale[OO];
__device__ float g_shift[OO];

// ---------------- K_zero ----------------
__global__ void k_zero() {
    int t = threadIdx.x;
    if (t < OO) { g_sum[t] = 0.f; g_sumsq[t] = 0.f; }
}

// ---------------- K_prep: sq, z, u ----------------
__global__ __launch_bounds__(256) void k_prep(const float* __restrict__ x,
                                              const float* __restrict__ W,
                                              const float* __restrict__ bias) {
    __shared__ float xs[32][65];
    __shared__ float W2s[64][65];
    __shared__ float Wds[64][65];

    int blk = blockIdx.x;
    int b   = blk >> 7;
    int n0  = (blk & 127) * 32;
    int tid = threadIdx.x;

    for (int i = tid; i < 64 * 64; i += 256) {
        int o = i >> 6, c = i & 63;
        float w1 = W[o * 128 + c];
        float w2 = W[o * 128 + 64 + c];
        W2s[o][c] = w2;
        Wds[o][c] = w1 - w2;
    }
    const float* xb = x + (size_t)b * CC * NN;
    for (int i = tid; i < 64 * 32; i += 256) {
        int c = i >> 5, j = i & 31;
        xs[j][c] = xb[c * NN + n0 + j];
    }
    __syncthreads();

    if (tid < 32) {
        float s = 0.f;
        #pragma unroll 16
        for (int c = 0; c < 64; c++) { float v = xs[tid][c]; s += v * v; }
        g_sq[b * NN + n0 + tid] = s;
    }

    for (int i = tid; i < 32 * 64; i += 256) {
        int j = i >> 6, o = i & 63;
        float za = 0.f, ua = bias[o];
        #pragma unroll 16
        for (int c = 0; c < 64; c++) {
            float xv = xs[j][c];
            za = fmaf(W2s[o][c], xv, za);
            ua = fmaf(Wds[o][c], xv, ua);
        }
        size_t pt = (size_t)(b * NN + n0 + j) * OO + o;
        g_z[pt] = za;
        g_u[pt] = ua;
    }
}

// ---------------- K_dist: symmetric pairwise d2, FFMA2 (f32x2) ----------------
__global__ __launch_bounds__(256) void k_dist(const float* __restrict__ x) {
    int b  = blockIdx.z;
    int ti = blockIdx.y;          // q tile 0..31
    int tj = blockIdx.x;          // m tile 0..31
    if (tj < ti) return;
    bool diag = (tj == ti);

    __shared__ float sQ[32][128];
    __shared__ float sM[32][128];

    int q0 = ti * 128, m0 = tj * 128;
    int tid = threadIdx.x;
    int tx = tid & 15, ty = tid >> 4;

    unsigned long long acc[8][4];
    #pragma unroll
    for (int i = 0; i < 8; i++)
        #pragma unroll
        for (int j = 0; j < 4; j++) acc[i][j] = 0ull;

    for (int h = 0; h < 2; h++) {
        __syncthreads();
        const float* xb = x + ((size_t)b * CC + h * 32) * NN;
        for (int t = tid; t < 32 * 128; t += 256) {
            int c = t >> 7, n = t & 127;
            sQ[c][n] = xb[c * NN + q0 + n];
            sM[c][n] = xb[c * NN + m0 + n];
        }
        __syncthreads();

        #pragma unroll 8
        for (int c = 0; c < 32; c++) {
            float4 a0 = *(const float4*)&sQ[c][ty * 8];
            float4 a1 = *(const float4*)&sQ[c][ty * 8 + 4];
            ulonglong2 bb0 = *(const ulonglong2*)&sM[c][tx * 8];
            ulonglong2 bb1 = *(const ulonglong2*)&sM[c][tx * 8 + 4];
            unsigned long long B0 = bb0.x, B1 = bb0.y, B2 = bb1.x, B3 = bb1.y;
            float av[8] = {a0.x, a0.y, a0.z, a0.w, a1.x, a1.y, a1.z, a1.w};
            #pragma unroll
            for (int i = 0; i < 8; i++) {
                unsigned long long A;
                asm("mov.b64 %0, {%1, %1};" : "=l"(A) : "f"(av[i]));
                asm("fma.rn.f32x2 %0, %1, %2, %3;" : "=l"(acc[i][0]) : "l"(A), "l"(B0), "l"(acc[i][0]));
                asm("fma.rn.f32x2 %0, %1, %2, %3;" : "=l"(acc[i][1]) : "l"(A), "l"(B1), "l"(acc[i][1]));
                asm("fma.rn.f32x2 %0, %1, %2, %3;" : "=l"(acc[i][2]) : "l"(A), "l"(B2), "l"(acc[i][2]));
                asm("fma.rn.f32x2 %0, %1, %2, %3;" : "=l"(acc[i][3]) : "l"(A), "l"(B3), "l"(acc[i][3]));
            }
        }
    }

    float d[8][8];
    #pragma unroll
    for (int i = 0; i < 8; i++)
        #pragma unroll
        for (int j = 0; j < 4; j++) {
            float lo, hi;
            asm("mov.b64 {%0, %1}, %2;" : "=f"(lo), "=f"(hi) : "l"(acc[i][j]));
            d[i][2 * j] = lo; d[i][2 * j + 1] = hi;
        }

    int qg0 = q0 + ty * 8, mg0 = m0 + tx * 8;
    float sqq[8], sqm[8];
    #pragma unroll
    for (int i = 0; i < 8; i++) {
        sqq[i] = g_sq[b * NN + qg0 + i];
        sqm[i] = g_sq[b * NN + mg0 + i];
    }
    #pragma unroll
    for (int i = 0; i < 8; i++)
        #pragma unroll
        for (int j = 0; j < 8; j++) {
            float v = (sqq[i] + sqm[j]) - 2.0f * d[i][j];
            d[i][j] = (diag && (qg0 + i == mg0 + j)) ? FLT_MAX : v;
        }

    float* base = g_d2 + ((size_t)b << 24);
    #pragma unroll
    for (int i = 0; i < 8; i++) {
        float* dst = base + (size_t)(qg0 + i) * NN + mg0;
        *(float4*)(dst)     = make_float4(d[i][0], d[i][1], d[i][2], d[i][3]);
        *(float4*)(dst + 4) = make_float4(d[i][4], d[i][5], d[i][6], d[i][7]);
    }
    if (!diag) {
        #pragma unroll
        for (int j = 0; j < 8; j++) {
            float* dst = base + (size_t)(mg0 + j) * NN + qg0;
            *(float4*)(dst)     = make_float4(d[0][j], d[1][j], d[2][j], d[3][j]);
            *(float4*)(dst + 4) = make_float4(d[4][j], d[5][j], d[6][j], d[7][j]);
        }
    }
}

// ---------------- K_select: warp per row, exact top-20 set ----------------
// Fast path: per-lane depth-4 value cache -> candidate threshold T.
// Exact rescan counts detect cache overflow (count(v<T) >= 20); rare rows
// fall back to exact packed-key extraction. Always writes exactly the
// true 20-smallest index set.
#define INS4(v) do { float t = (v); \
    float n0 = fminf(t, m0); t = fmaxf(t, m0); m0 = n0; \
    float n1 = fminf(t, m1); t = fmaxf(t, m1); m1 = n1; \
    float n2 = fminf(t, m2); t = fmaxf(t, m2); m2 = n2; \
    m3 = fminf(t, m3); } while (0)

__global__ __launch_bounds__(256) void k_select() {
    int row  = (blockIdx.x << 3) + (threadIdx.x >> 5);   // b*N + n
    int lane = threadIdx.x & 31;
    const float4* dr4 = (const float4*)(g_d2 + (size_t)row * NN);

    // phase 1: per-lane sorted top-4 values
    float m0 = FLT_MAX, m1 = FLT_MAX, m2 = FLT_MAX, m3 = FLT_MAX;
    #pragma unroll 8
    for (int e = 0; e < 32; e++) {
        float4 v = dr4[e * 32 + lane];
        INS4(v.x); INS4(v.y); INS4(v.z); INS4(v.w);
    }

    // phase 2: 20 extraction rounds -> candidate threshold T
    float T = 0.f;
    for (int r = 0; r < KK; r++) {
        float w = m0;
        #pragma unroll
        for (int s = 16; s; s >>= 1)
            w = fminf(w, __shfl_xor_sync(0xFFFFFFFFu, w, s));
        unsigned msk = __ballot_sync(0xFFFFFFFFu, m0 == w);
        if (lane == __ffs(msk) - 1) {
            m0 = m1; m1 = m2; m2 = m3; m3 = FLT_MAX;
        }
        T = w;
    }

    // phase 3a: exact per-lane counts of v<T and v==T
    int cl = 0, ce = 0;
    #pragma unroll 4
    for (int e = 0; e < 32; e++) {
        float4 v = dr4[e * 32 + lane];
        cl += (v.x < T) + (v.y < T) + (v.z < T) + (v.w < T);
        ce += (v.x == T) + (v.y == T) + (v.z == T) + (v.w == T);
    }
    int offL = cl, offE = ce;
    #pragma unroll
    for (int s = 1; s < 32; s <<= 1) {
        int a = __shfl_up_sync(0xFFFFFFFFu, offL, s);
        int bq = __shfl_up_sync(0xFFFFFFFFu, offE, s);
        if (lane >= s) { offL += a; offE += bq; }
    }
    int LT = __shfl_sync(0xFFFFFFFFu, offL, 31);   // total v<T
    offL -= cl;
    offE -= ce;

    if (LT < KK) {
        // fast path: T is the true 20th value
        int needE = KK - LT;
        int wl = row * KK + offL;
        int er = offE;
        #pragma unroll 4
        for (int e = 0; e < 32; e++) {
            float4 v = dr4[e * 32 + lane];
            int bi = e * 128 + lane * 4;
            if (v.x < T) g_idx[wl++] = bi;
            else if (v.x == T) { if (er < needE) g_idx[row * KK + LT + er] = bi; er++; }
            if (v.y < T) g_idx[wl++] = bi + 1;
            else if (v.y == T) { if (er < needE) g_idx[row * KK + LT + er] = bi + 1; er++; }
            if (v.z < T) g_idx[wl++] = bi + 2;
            else if (v.z == T) { if (er < needE) g_idx[row * KK + LT + er] = bi + 2; er++; }
            if (v.w < T) g_idx[wl++] = bi + 3;
            else if (v.w == T) { if (er < needE) g_idx[row * KK + LT + er] = bi + 3; er++; }
        }
    } else {
        // fallback (cache overflowed): exact packed-key extraction, L1-hot row
        unsigned long long last = 0ull;
        for (int r = 0; r < KK; r++) {
            unsigned long long lm = 0xFFFFFFFFFFFFFFFFull;
            #pragma unroll 4
            for (int e = 0; e < 32; e++) {
                float4 v = dr4[e * 32 + lane];
                unsigned bi = (unsigned)(e * 128 + lane * 4);
                unsigned long long k0 = ((unsigned long long)__float_as_uint(v.x) << 32) | bi;
                unsigned long long k1 = ((unsigned long long)__float_as_uint(v.y) << 32) | (bi + 1);
                unsigned long long k2 = ((unsigned long long)__float_as_uint(v.z) << 32) | (bi + 2);
                unsigned long long k3 = ((unsigned long long)__float_as_uint(v.w) << 32) | (bi + 3);
                if (k0 > last && k0 < lm) lm = k0;
                if (k1 > last && k1 < lm) lm = k1;
                if (k2 > last && k2 < lm) lm = k2;
                if (k3 > last && k3 < lm) lm = k3;
            }
            unsigned long long w = lm;
            #pragma unroll
            for (int s = 16; s; s >>= 1) {
                unsigned long long o = __shfl_xor_sync(0xFFFFFFFFu, w, s);
                if (o < w) w = o;
            }
            if (lane == 0) g_idx[row * KK + r] = (int)(w & 0xFFFFFFFFu);
            last = w;
        }
    }
}

// ---------------- K_gather: ymax + BN stats ----------------
__global__ __launch_bounds__(256) void k_gather() {
    __shared__ float s[256];
    int tid = threadIdx.x;
    int pl = tid >> 6, o = tid & 63;
    float rs1 = 0.f, rs2 = 0.f;

    #pragma unroll
    for (int it = 0; it < 4; it++) {
        int pt = blockIdx.x * 16 + it * 4 + pl;
        int zbase = pt & ~(NN - 1);
        float u = g_u[(size_t)pt * OO + o];
        float m = -FLT_MAX, s1 = 0.f, s2 = 0.f;
        #pragma unroll
        for (int k = 0; k < KK; k++) {
            int nbr = __ldg(&g_idx[pt * KK + k]);
            float z = g_z[(size_t)(zbase + nbr) * OO + o];
            m = fmaxf(m, z);
            s1 += z;
            s2 = fmaf(z, z, s2);
        }
        g_ymax[(size_t)pt * OO + o] = u + m;
        rs1 += 20.f * u + s1;
        rs2 += fmaf(20.f * u, u, fmaf(2.f * u, s1, s2));
    }
    s[tid] = rs1; __syncthreads();
    if (pl == 0) atomicAdd(&g_sum[o], s[o] + s[o + 64] + s[o + 128] + s[o + 192]);
    __syncthreads();
    s[tid] = rs2; __syncthreads();
    if (pl == 0) atomicAdd(&g_sumsq[o], s[o] + s[o + 64] + s[o + 128] + s[o + 192]);
}

// ---------------- K_stats ----------------
__global__ void k_stats(const float* __restrict__ gamma, const float* __restrict__ beta) {
    int o = threadIdx.x;
    if (o < OO) {
        float mean = g_sum[o] / BNK;
        float var  = g_sumsq[o] / BNK - mean * mean;
        float sc   = gamma[o] * rsqrtf(var + 1e-5f);
        g_scale[o] = sc;
        g_shift[o] = beta[o] - mean * sc;
    }
}

// ---------------- K_final ----------------
__global__ __launch_bounds__(256) void k_final(float* __restrict__ out) {
    __shared__ float t[64][33];
    int b  = blockIdx.x >> 7;
    int n0 = (blockIdx.x & 127) << 5;
    int tid = threadIdx.x;

    for (int i = tid; i < 2048; i += 256) {
        int r = i >> 6, c = i & 63;
        t[c][r] = g_ymax[(size_t)((b << 12) + n0 + r) * OO + c];
    }
    __syncthreads();
    for (int i = tid; i < 2048; i += 256) {
        int o = i >> 5, nl = i & 31;
        float v = fmaf(t[o][nl], g_scale[o], g_shift[o]);
        out[(size_t)b * OO * NN + (size_t)o * NN + n0 + nl] = fmaxf(v, 0.f);
    }
}

// ---------------- launch ----------------
extern "C" void kernel_launch(void* const* d_in, const int* in_sizes, int n_in,
                              void* d_out, int out_size) {
    const float* x     = (const float*)d_in[0];
    const float* W     = (const float*)d_in[1];
    const float* bias  = (const float*)d_in[2];
    const float* gamma = (const float*)d_in[3];
    const float* beta  = (const float*)d_in[4];
    float* out = (float*)d_out;

    k_zero<<<1, 128>>>();
    k_prep<<<1024, 256>>>(x, W, bias);
    dim3 gd(32, 32, BB);
    k_dist<<<gd, 256>>>(x);
    k_select<<<BB * NN / 8, 256>>>();
    k_gather<<<2048, 256>>>();
    k_stats<<<1, 64>>>(gamma, beta);
    k_final<<<1024, 256>>>(out);
}